// round 14
// baseline (speedup 1.0000x reference)
#include <cuda_runtime.h>
#include <cuda_fp16.h>
#include <cstdint>

#define BGN 8    // B*G
#define HH  16   // heads
#define NN  1024 // sequence
#define NHEADS (BGN*HH) // 128

// Q pre-scale: 1/sqrt(64) * log2(e)  (softmax in exp2 domain, no max sub)
#define QSCALE 0.18033688011112042f
#define ONES_H2 0x3C003C00u
// Global exponent shift: p = 2^(s-5) * exp(-bias); cancels in normalization.
#define SHIFT (-5.0f)

// Scratch (static __device__ per harness rules)
__device__ __half g_Q[(size_t)NHEADS * NN * 64]; // fp16, pre-scaled
__device__ __half g_K[(size_t)NHEADS * NN * 64]; // fp16
__device__ __half g_V[(size_t)NHEADS * NN * 64]; // fp16
// exp(-bias), fp16, PERMUTED within each 64-col tile:
//   col c (0..63): nb=c>>3, qc=(c&7)>>1, e=c&1  ->  pos = qc*16 + nb*2 + e
__device__ __half g_EB[(size_t)4 * NN * NN];

__device__ __forceinline__ uint32_t h2u(float lo, float hi) {
    __half2 h = __floats2half2_rn(lo, hi);
    return *reinterpret_cast<uint32_t*>(&h);
}

__device__ __forceinline__ uint32_t ex2h2(uint32_t a) {
    uint32_t r;
    asm("ex2.approx.f16x2 %0, %1;" : "=r"(r) : "r"(a));
    return r;
}

__device__ __forceinline__ uint32_t hmul2u(uint32_t a, uint32_t b) {
    __half2 r = __hmul2(*reinterpret_cast<__half2*>(&a),
                        *reinterpret_cast<__half2*>(&b));
    return *reinterpret_cast<uint32_t*>(&r);
}

__device__ __forceinline__ void cp16(void* dst, const void* src) {
    uint32_t d = (uint32_t)__cvta_generic_to_shared(dst);
    asm volatile("cp.async.cg.shared.global [%0], [%1], 16;" :: "r"(d), "l"(src));
}

__device__ __forceinline__ void mma_f16(float c[4], const uint32_t a[4],
                                        uint32_t b0, uint32_t b1) {
    asm volatile(
        "mma.sync.aligned.m16n8k16.row.col.f32.f16.f16.f32 "
        "{%0,%1,%2,%3}, {%4,%5,%6,%7}, {%8,%9}, {%0,%1,%2,%3};"
        : "+f"(c[0]), "+f"(c[1]), "+f"(c[2]), "+f"(c[3])
        : "r"(a[0]), "r"(a[1]), "r"(a[2]), "r"(a[3]), "r"(b0), "r"(b1));
}

__device__ __forceinline__ void ldsm4(uint32_t& r0, uint32_t& r1, uint32_t& r2,
                                      uint32_t& r3, uint32_t addr) {
    asm volatile("ldmatrix.sync.aligned.m8n8.x4.shared.b16 {%0,%1,%2,%3}, [%4];"
                 : "=r"(r0), "=r"(r1), "=r"(r2), "=r"(r3) : "r"(addr));
}

__device__ __forceinline__ void ldsm4t(uint32_t& r0, uint32_t& r1, uint32_t& r2,
                                       uint32_t& r3, uint32_t addr) {
    asm volatile("ldmatrix.sync.aligned.m8n8.x4.trans.shared.b16 {%0,%1,%2,%3}, [%4];"
                 : "=r"(r0), "=r"(r1), "=r"(r2), "=r"(r3) : "r"(addr));
}

// ---------------------------------------------------------------------------
// prep chunk: CTAs [0, eb_ctas): EB planes from g=eb_g0 (permuted, MLP=4).
//             CTAs [eb_ctas, eb_ctas+512): pack 2 bg starting at bg0.
// 32 regs/thread so one prep CTA co-resides with two 224-reg attn CTAs.
// ---------------------------------------------------------------------------
__global__ void __launch_bounds__(256, 8)
prep_kernel(const float* __restrict__ q,
            const float* __restrict__ k,
            const float* __restrict__ v,
            const float* __restrict__ b,
            int eb_g0, int bg0, int eb_ctas) {
    __shared__ float sm3[3][4][1024]; // 48 KB
    const int t = threadIdx.x;

    if ((int)blockIdx.x < eb_ctas) {
        // EB: 4 float4 per thread, loads front-batched (MLP=4)
        const int base = eb_g0 * (NN * NN / 4) + blockIdx.x * 1024;
        float4 x[4];
#pragma unroll
        for (int kk = 0; kk < 4; kk++)
            x[kk] = ((const float4*)b)[base + kk * 256 + t];
#pragma unroll
        for (int kk = 0; kk < 4; kk++) {
            int i = base + kk * 256 + t;
            uint32_t ylo = h2u(__expf(-x[kk].x), __expf(-x[kk].y));
            uint32_t yhi = h2u(__expf(-x[kk].z), __expf(-x[kk].w));
            int m = (i * 4) & 1023;              // col of first element
            int row = (i * 4) >> 10;
            int jt = m >> 6, c = m & 63;
            int nb = c >> 3, qc = (c & 7) >> 1;  // qc in {0,2}
            uint32_t* tb = (uint32_t*)(g_EB + (size_t)row * 1024 + jt * 64);
            tb[qc * 8 + nb]       = ylo;         // cols m, m+1
            tb[(qc + 1) * 8 + nb] = yhi;         // cols m+2, m+3
        }
        return;
    }

    const int bx = blockIdx.x - eb_ctas;     // 0..511
    const int n0 = (bx & 255) * 4, bg = bg0 + (bx >> 8);
    const size_t off = ((size_t)bg * NN + n0) * 1024;
    const int g4 = t ^ ((t >> 4) & 7);       // within-token float4 swizzle

    // front-batched loads: 12 LDG.128 in flight before any use
    float4 lq[4], lk[4], lv[4];
#pragma unroll
    for (int tt = 0; tt < 4; tt++) lq[tt] = ((const float4*)(q + off))[tt * 256 + t];
#pragma unroll
    for (int tt = 0; tt < 4; tt++) lk[tt] = ((const float4*)(k + off))[tt * 256 + t];
#pragma unroll
    for (int tt = 0; tt < 4; tt++) lv[tt] = ((const float4*)(v + off))[tt * 256 + t];
#pragma unroll
    for (int tt = 0; tt < 4; tt++) {
        ((float4*)sm3[0][tt])[g4] = lq[tt];
        ((float4*)sm3[1][tt])[g4] = lk[tt];
        ((float4*)sm3[2][tt])[g4] = lv[tt];
    }
    __syncthreads();

#define SWIDX(e) (((((e) >> 2) ^ ((((e) >> 2) >> 4) & 7)) << 2) | ((e) & 3))
#pragma unroll
    for (int half = 0; half < 2; half++) {
        const int tt = (t >> 7) + half * 2;  // token
        const int r  = t & 127;
        const int h  = r >> 3;               // head
        const int d0 = (r & 7) * 8;          // 8-d group
        const size_t ooff = (((size_t)bg * HH + h) * NN + n0 + tt) * 64 + d0;

        float qv[8], kv[8], vv[8];
#pragma unroll
        for (int i = 0; i < 8; i++) {
            int e = (d0 + i) * 16 + h;
            int s = SWIDX(e);
            qv[i] = sm3[0][tt][s] * QSCALE;
            kv[i] = sm3[1][tt][s];
            vv[i] = sm3[2][tt][s];
        }
        union { uint32_t u[4]; uint4 q4; } oq, ok, ov;
#pragma unroll
        for (int i = 0; i < 4; i++) {
            oq.u[i] = h2u(qv[2 * i], qv[2 * i + 1]);
            ok.u[i] = h2u(kv[2 * i], kv[2 * i + 1]);
            ov.u[i] = h2u(vv[2 * i], vv[2 * i + 1]);
        }
        *(uint4*)(g_Q + ooff) = oq.q4;
        *(uint4*)(g_K + ooff) = ok.q4;
        *(uint4*)(g_V + ooff) = ov.q4;
    }
#undef SWIDX
}

// ---------------------------------------------------------------------------
// Flash attention: 4 warps x 32 rows, 4-stage cp.async, one barrier/iter,
// 2 CTAs/SM, permuted-EB vector loads. __launch_bounds__(144,2) caps regs at
// 224 so one 32-reg prep CTA co-resides per SM (overlap via fork-join).
// ---------------------------------------------------------------------------
#define BR 128
#define BC 64
#define STAGES 4

struct Smem {
    __half K[STAGES][BC * 64];
    __half V[STAGES][BC * 64];
};
static constexpr int SMEM_BYTES = sizeof(Smem); // 64 KB

__device__ __forceinline__ void load_kv(char* smk, char* smv, const __half* kbase,
                                        const __half* vbase, int j, int tid) {
    const __half* kp = kbase + (size_t)j * BC * 64;
    const __half* vp = vbase + (size_t)j * BC * 64;
#pragma unroll
    for (int i = 0; i < 4; i++) {
        int c = tid + i * 128;          // 0..511
        int r = c >> 3, ch = c & 7;
        int dst = r * 128 + ((ch ^ (r & 7)) << 4);
        cp16(smk + dst, kp + r * 64 + ch * 8);
        cp16(smv + dst, vp + r * 64 + ch * 8);
    }
}

__global__ void __launch_bounds__(144, 2)
attn_kernel(float* __restrict__ out, int bg_base) {
    extern __shared__ char smraw[];
    Smem* sm = (Smem*)smraw;

    const int tid = threadIdx.x;
    const int lane = tid & 31, wid = tid >> 5;   // wid 0..3
    const int bg = bg_base + blockIdx.z;
    const int hd = bg * HH + blockIdx.y;
    const int g  = bg & 3;
    const int n0 = blockIdx.x * BR;
    const int ql = lane >> 2, qc = lane & 3;

    // Q fp16 A-fragments, resident: 2 m-halves x 4 k-blocks
    const __half* qp = g_Q + (((size_t)hd) * NN + n0 + wid * 32) * 64;
    uint32_t qa[2][4][4];
#pragma unroll
    for (int mh = 0; mh < 2; mh++)
#pragma unroll
        for (int kb = 0; kb < 4; kb++) {
            const __half* qr = qp + (mh * 16) * 64;
            qa[mh][kb][0] = *(const uint32_t*)(qr + (ql)     * 64 + kb * 16 + qc * 2);
            qa[mh][kb][1] = *(const uint32_t*)(qr + (ql + 8) * 64 + kb * 16 + qc * 2);
            qa[mh][kb][2] = *(const uint32_t*)(qr + (ql)     * 64 + kb * 16 + qc * 2 + 8);
            qa[mh][kb][3] = *(const uint32_t*)(qr + (ql + 8) * 64 + kb * 16 + qc * 2 + 8);
        }

    float o[2][8][4];
#pragma unroll
    for (int mh = 0; mh < 2; mh++)
#pragma unroll
        for (int nb = 0; nb < 8; nb++)
            o[mh][nb][0] = o[mh][nb][1] = o[mh][nb][2] = o[mh][nb][3] = 0.f;
    float lacc[2][4] = {{0.f, 0.f, 0.f, 0.f}, {0.f, 0.f, 0.f, 0.f}};

    const __half* kbase = g_K + ((size_t)hd) * NN * 64;
    const __half* vbase = g_V + ((size_t)hd) * NN * 64;

#pragma unroll
    for (int s = 0; s < 3; s++) {
        load_kv((char*)sm->K[s], (char*)sm->V[s], kbase, vbase, s, tid);
        asm volatile("cp.async.commit_group;");
    }

    // permuted-EB base: row (n0 + wid*32 + ql), within-tile offset qc*16
    const __half* ebbase =
        g_EB + ((size_t)g * NN + (n0 + wid * 32 + ql)) * NN + qc * 16;

#pragma unroll 1
    for (int j = 0; j < 16; j++) {
        const int buf = j & (STAGES - 1);

        // exp(-bias) fragments: 8 x LDG.128 (32B contiguous per row-half)
        uint32_t ebA[2][8], ebB[2][8];
#pragma unroll
        for (int mh = 0; mh < 2; mh++) {
            const __half* erA = ebbase + (size_t)(mh * 16) * NN + j * 64;
            const __half* erB = erA + (size_t)8 * NN;
            uint4 a0 = *(const uint4*)(erA);
            uint4 a1 = *(const uint4*)(erA + 8);
            uint4 b0 = *(const uint4*)(erB);
            uint4 b1 = *(const uint4*)(erB + 8);
            ebA[mh][0] = a0.x; ebA[mh][1] = a0.y; ebA[mh][2] = a0.z; ebA[mh][3] = a0.w;
            ebA[mh][4] = a1.x; ebA[mh][5] = a1.y; ebA[mh][6] = a1.z; ebA[mh][7] = a1.w;
            ebB[mh][0] = b0.x; ebB[mh][1] = b0.y; ebB[mh][2] = b0.z; ebB[mh][3] = b0.w;
            ebB[mh][4] = b1.x; ebB[mh][5] = b1.y; ebB[mh][6] = b1.z; ebB[mh][7] = b1.w;
        }

        if (j <= 13)      asm volatile("cp.async.wait_group 2;");
        else if (j == 14) asm volatile("cp.async.wait_group 1;");
        else              asm volatile("cp.async.wait_group 0;");
        __syncthreads();

        if (j + 3 < 16) {
            int nxt = (j + 3) & (STAGES - 1);
            load_kv((char*)sm->K[nxt], (char*)sm->V[nxt], kbase, vbase, j + 3, tid);
            asm volatile("cp.async.commit_group;");
        }

        // ---- S = Q K^T + SHIFT; each B-frag feeds both m-halves ----
        float s[2][8][4];
#pragma unroll
        for (int mh = 0; mh < 2; mh++)
#pragma unroll
            for (int nb = 0; nb < 8; nb++)
                s[mh][nb][0] = s[mh][nb][1] = s[mh][nb][2] = s[mh][nb][3] = SHIFT;
        {
            char* kb_sm = (char*)sm->K[buf];
            const int m = lane >> 3, r = lane & 7;
#pragma unroll
            for (int kb = 0; kb < 4; kb++) {
#pragma unroll
                for (int nbp = 0; nbp < 4; nbp++) {
                    int n = nbp * 16 + ((m >> 1) << 3) + r;
                    int ch = kb * 2 + (m & 1);
                    uint32_t addr = (uint32_t)__cvta_generic_to_shared(
                        kb_sm + n * 128 + ((ch ^ (n & 7)) << 4));
                    uint32_t b0, b1, b2, b3;
                    ldsm4(b0, b1, b2, b3, addr);
                    mma_f16(s[0][2 * nbp],     qa[0][kb], b0, b1);
                    mma_f16(s[0][2 * nbp + 1], qa[0][kb], b2, b3);
                    mma_f16(s[1][2 * nbp],     qa[1][kb], b0, b1);
                    mma_f16(s[1][2 * nbp + 1], qa[1][kb], b2, b3);
                }
            }
        }

        // ---- p = 2^(s-5) * exp(-bias) ----
        uint32_t pa[2][4][4];
#pragma unroll
        for (int mh = 0; mh < 2; mh++)
#pragma unroll
            for (int kb2 = 0; kb2 < 4; kb2++) {
                pa[mh][kb2][0] = hmul2u(ex2h2(h2u(s[mh][2*kb2][0],   s[mh][2*kb2][1])),   ebA[mh][2*kb2]);
                pa[mh][kb2][1] = hmul2u(ex2h2(h2u(s[mh][2*kb2][2],   s[mh][2*kb2][3])),   ebB[mh][2*kb2]);
                pa[mh][kb2][2] = hmul2u(ex2h2(h2u(s[mh][2*kb2+1][0], s[mh][2*kb2+1][1])), ebA[mh][2*kb2+1]);
                pa[mh][kb2][3] = hmul2u(ex2h2(h2u(s[mh][2*kb2+1][2], s[mh][2*kb2+1][3])), ebB[mh][2*kb2+1]);
            }

        // ---- l += P * ones (tensor-core row sum) ----
#pragma unroll
        for (int mh = 0; mh < 2; mh++)
#pragma unroll
            for (int kb2 = 0; kb2 < 4; kb2++)
                mma_f16(lacc[mh], pa[mh][kb2], ONES_H2, ONES_H2);

        // ---- O += P V; each V-frag feeds both m-halves ----
        {
            char* vb_sm = (char*)sm->V[buf];
            const int lr = lane & 7, lm = lane >> 3;
#pragma unroll
            for (int kb2 = 0; kb2 < 4; kb2++) {
                const int krow = kb2 * 16 + lr + ((lm & 1) << 3);
#pragma unroll
                for (int nb2 = 0; nb2 < 4; nb2++) {
                    const int ch = nb2 * 2 + ((lm >> 1) & 1);
                    uint32_t addr = (uint32_t)__cvta_generic_to_shared(
                        vb_sm + krow * 128 + ((ch ^ (krow & 7)) << 4));
                    uint32_t v0, v1, v2, v3;
                    ldsm4t(v0, v1, v2, v3, addr);
                    mma_f16(o[0][nb2 * 2],     pa[0][kb2], v0, v1);
                    mma_f16(o[0][nb2 * 2 + 1], pa[0][kb2], v2, v3);
                    mma_f16(o[1][nb2 * 2],     pa[1][kb2], v0, v1);
                    mma_f16(o[1][nb2 * 2 + 1], pa[1][kb2], v2, v3);
                }
            }
        }
    }

    // ---- epilogue: normalize + store ----
#pragma unroll
    for (int mh = 0; mh < 2; mh++) {
        const float inv0 = 1.0f / lacc[mh][0], inv1 = 1.0f / lacc[mh][2];
        float* op = out + (((size_t)hd) * NN + n0 + wid * 32 + mh * 16 + ql) * 64 + qc * 2;
#pragma unroll
        for (int nb = 0; nb < 8; nb++) {
            float2 a = make_float2(o[mh][nb][0] * inv0, o[mh][nb][1] * inv0);
            float2 b = make_float2(o[mh][nb][2] * inv1, o[mh][nb][3] * inv1);
            *(float2*)(op + nb * 8) = a;
            *(float2*)(op + 8 * 64 + nb * 8) = b;
        }
    }
}

// ---------------------------------------------------------------------------
// Fork-join streams/events: created once at static init (outside any capture).
// ---------------------------------------------------------------------------
static cudaStream_t s_sa = nullptr, s_sb = nullptr;
static cudaEvent_t  s_ev[4] = {nullptr, nullptr, nullptr, nullptr};
static cudaEvent_t  s_ja = nullptr, s_jb = nullptr;
static bool s_ok = false;

namespace {
struct StreamInit {
    StreamInit() {
        bool ok = true;
        ok &= cudaStreamCreateWithFlags(&s_sa, cudaStreamNonBlocking) == cudaSuccess;
        ok &= cudaStreamCreateWithFlags(&s_sb, cudaStreamNonBlocking) == cudaSuccess;
        for (int i = 0; i < 4; i++)
            ok &= cudaEventCreateWithFlags(&s_ev[i], cudaEventDisableTiming) == cudaSuccess;
        ok &= cudaEventCreateWithFlags(&s_ja, cudaEventDisableTiming) == cudaSuccess;
        ok &= cudaEventCreateWithFlags(&s_jb, cudaEventDisableTiming) == cudaSuccess;
        s_ok = ok;
    }
} s_stream_init;
}

extern "C" void kernel_launch(void* const* d_in, const int* in_sizes, int n_in,
                              void* d_out, int out_size) {
    const float* q    = (const float*)d_in[0];
    const float* k    = (const float*)d_in[1];
    const float* v    = (const float*)d_in[2];
    const float* bias = (const float*)d_in[3];
    float* out = (float*)d_out;

    cudaFuncSetAttribute(attn_kernel, cudaFuncAttributeMaxDynamicSharedMemorySize,
                         SMEM_BYTES);

    if (s_ok) {
        // p0: EB g{0,1} + pack bg{0,1}   (null = capture-origin stream)
        prep_kernel<<<1024, 256>>>(q, k, v, bias, 0, 0, 512);
        cudaEventRecord(s_ev[0], 0);
        // p1: EB g{2,3} + pack bg{2,3}
        prep_kernel<<<1024, 256>>>(q, k, v, bias, 2, 2, 512);
        cudaEventRecord(s_ev[1], 0);
        // p2: pack bg{4,5}
        prep_kernel<<<512, 256>>>(q, k, v, bias, 0, 4, 0);
        cudaEventRecord(s_ev[2], 0);
        // p3: pack bg{6,7}
        prep_kernel<<<512, 256>>>(q, k, v, bias, 0, 6, 0);
        cudaEventRecord(s_ev[3], 0);

        cudaStreamWaitEvent(s_sa, s_ev[0], 0);
        attn_kernel<<<dim3(NN / BR, HH, 2), 128, SMEM_BYTES, s_sa>>>(out, 0);
        cudaStreamWaitEvent(s_sb, s_ev[1], 0);
        attn_kernel<<<dim3(NN / BR, HH, 2), 128, SMEM_BYTES, s_sb>>>(out, 2);
        cudaStreamWaitEvent(s_sa, s_ev[2], 0);
        attn_kernel<<<dim3(NN / BR, HH, 2), 128, SMEM_BYTES, s_sa>>>(out, 4);
        cudaStreamWaitEvent(s_sb, s_ev[3], 0);
        attn_kernel<<<dim3(NN / BR, HH, 2), 128, SMEM_BYTES, s_sb>>>(out, 6);

        // join both side streams back into the origin stream
        cudaEventRecord(s_ja, s_sa);
        cudaEventRecord(s_jb, s_sb);
        cudaStreamWaitEvent(0, s_ja, 0);
        cudaStreamWaitEvent(0, s_jb, 0);
    } else {
        // serial fallback (identical math)
        prep_kernel<<<1024, 256>>>(q, k, v, bias, 0, 0, 512);
        prep_kernel<<<1024, 256>>>(q, k, v, bias, 2, 2, 512);
        prep_kernel<<<512, 256>>>(q, k, v, bias, 0, 4, 0);
        prep_kernel<<<512, 256>>>(q, k, v, bias, 0, 6, 0);
        attn_kernel<<<dim3(NN / BR, HH, 2), 128, SMEM_BYTES>>>(out, 0);
        attn_kernel<<<dim3(NN / BR, HH, 2), 128, SMEM_BYTES>>>(out, 2);
        attn_kernel<<<dim3(NN / BR, HH, 2), 128, SMEM_BYTES>>>(out, 4);
        attn_kernel<<<dim3(NN / BR, HH, 2), 128, SMEM_BYTES>>>(out, 6);
    }
}

// round 15
// speedup vs baseline: 1.7828x; 1.7828x over previous
#include <cuda_runtime.h>
#include <cuda_fp16.h>
#include <cstdint>

#define BGN 8    // B*G
#define HH  16   // heads
#define NN  1024 // sequence
#define NHEADS (BGN*HH) // 128

// Q pre-scale: 1/sqrt(64) * log2(e)  (softmax in exp2 domain, no max sub)
#define QSCALE 0.18033688011112042f
#define ONES_H2 0x3C003C00u
// Global exponent shift: p = 2^(s-5) * exp(-bias); cancels in normalization.
#define SHIFT (-5.0f)

// Scratch (static __device__ per harness rules)
__device__ __half g_Q[(size_t)NHEADS * NN * 64]; // fp16, pre-scaled
__device__ __half g_K[(size_t)NHEADS * NN * 64]; // fp16
__device__ __half g_V[(size_t)NHEADS * NN * 64]; // fp16
// exp(-bias), fp16, PERMUTED within each 64-col tile:
//   col c (0..63): nb=c>>3, qc=(c&7)>>1, e=c&1  ->  pos = qc*16 + nb*2 + e
__device__ __half g_EB[(size_t)4 * NN * NN];

__device__ __forceinline__ uint32_t h2u(float lo, float hi) {
    __half2 h = __floats2half2_rn(lo, hi);
    return *reinterpret_cast<uint32_t*>(&h);
}

__device__ __forceinline__ uint32_t ex2h2(uint32_t a) {
    uint32_t r;
    asm("ex2.approx.f16x2 %0, %1;" : "=r"(r) : "r"(a));
    return r;
}

__device__ __forceinline__ uint32_t hmul2u(uint32_t a, uint32_t b) {
    __half2 r = __hmul2(*reinterpret_cast<__half2*>(&a),
                        *reinterpret_cast<__half2*>(&b));
    return *reinterpret_cast<uint32_t*>(&r);
}

__device__ __forceinline__ uint32_t hadd2u(uint32_t a, uint32_t b) {
    __half2 r = __hadd2(*reinterpret_cast<__half2*>(&a),
                        *reinterpret_cast<__half2*>(&b));
    return *reinterpret_cast<uint32_t*>(&r);
}

__device__ __forceinline__ void cp16(void* dst, const void* src) {
    uint32_t d = (uint32_t)__cvta_generic_to_shared(dst);
    asm volatile("cp.async.cg.shared.global [%0], [%1], 16;" :: "r"(d), "l"(src));
}

__device__ __forceinline__ void mma_f16(float c[4], const uint32_t a[4],
                                        uint32_t b0, uint32_t b1) {
    asm volatile(
        "mma.sync.aligned.m16n8k16.row.col.f32.f16.f16.f32 "
        "{%0,%1,%2,%3}, {%4,%5,%6,%7}, {%8,%9}, {%0,%1,%2,%3};"
        : "+f"(c[0]), "+f"(c[1]), "+f"(c[2]), "+f"(c[3])
        : "r"(a[0]), "r"(a[1]), "r"(a[2]), "r"(a[3]), "r"(b0), "r"(b1));
}

__device__ __forceinline__ void ldsm4(uint32_t& r0, uint32_t& r1, uint32_t& r2,
                                      uint32_t& r3, uint32_t addr) {
    asm volatile("ldmatrix.sync.aligned.m8n8.x4.shared.b16 {%0,%1,%2,%3}, [%4];"
                 : "=r"(r0), "=r"(r1), "=r"(r2), "=r"(r3) : "r"(addr));
}

__device__ __forceinline__ void ldsm4t(uint32_t& r0, uint32_t& r1, uint32_t& r2,
                                       uint32_t& r3, uint32_t addr) {
    asm volatile("ldmatrix.sync.aligned.m8n8.x4.trans.shared.b16 {%0,%1,%2,%3}, [%4];"
                 : "=r"(r0), "=r"(r1), "=r"(r2), "=r"(r3) : "r"(addr));
}

// ---------------------------------------------------------------------------
// prep: flattened grid.
//   CTAs [0,512):       g_EB = fp16(exp(-bias)), permuted; 8 float4/thread
//                       front-batched (MLP=8).
//   CTAs [512,2560):    pack [BG, N, d*16+h] -> head-major fp16, 4 tokens/CTA.
// ---------------------------------------------------------------------------
__global__ void prep_kernel(const float* __restrict__ q,
                            const float* __restrict__ k,
                            const float* __restrict__ v,
                            const float* __restrict__ b) {
    __shared__ float sm3[3][4][1024]; // 48 KB
    const int t = threadIdx.x;

    if (blockIdx.x < 512) {
        // EB: 8 float4 per thread, loads front-batched (MLP=8)
        const int base = blockIdx.x * 2048;
        float4 x[8];
#pragma unroll
        for (int kk = 0; kk < 8; kk++)
            x[kk] = ((const float4*)b)[base + kk * 256 + t];
#pragma unroll
        for (int kk = 0; kk < 8; kk++) {
            int i = base + kk * 256 + t;
            uint32_t ylo = h2u(__expf(-x[kk].x), __expf(-x[kk].y));
            uint32_t yhi = h2u(__expf(-x[kk].z), __expf(-x[kk].w));
            int m = (i * 4) & 1023;              // col of first element
            int row = (i * 4) >> 10;
            int jt = m >> 6, c = m & 63;
            int nb = c >> 3, qc = (c & 7) >> 1;  // qc in {0,2}
            uint32_t* tb = (uint32_t*)(g_EB + (size_t)row * 1024 + jt * 64);
            tb[qc * 8 + nb]       = ylo;         // cols m, m+1
            tb[(qc + 1) * 8 + nb] = yhi;         // cols m+2, m+3
        }
        return;
    }

    const int bx = blockIdx.x - 512;         // 0..2047
    const int n0 = (bx & 255) * 4, bg = bx >> 8;
    const size_t off = ((size_t)bg * NN + n0) * 1024;
    const int g4 = t ^ ((t >> 4) & 7);       // within-token float4 swizzle

    // front-batched loads: 12 LDG.128 in flight before any use
    float4 lq[4], lk[4], lv[4];
#pragma unroll
    for (int tt = 0; tt < 4; tt++) lq[tt] = ((const float4*)(q + off))[tt * 256 + t];
#pragma unroll
    for (int tt = 0; tt < 4; tt++) lk[tt] = ((const float4*)(k + off))[tt * 256 + t];
#pragma unroll
    for (int tt = 0; tt < 4; tt++) lv[tt] = ((const float4*)(v + off))[tt * 256 + t];
#pragma unroll
    for (int tt = 0; tt < 4; tt++) {
        ((float4*)sm3[0][tt])[g4] = lq[tt];
        ((float4*)sm3[1][tt])[g4] = lk[tt];
        ((float4*)sm3[2][tt])[g4] = lv[tt];
    }
    __syncthreads();

#define SWIDX(e) (((((e) >> 2) ^ ((((e) >> 2) >> 4) & 7)) << 2) | ((e) & 3))
#pragma unroll
    for (int half = 0; half < 2; half++) {
        const int tt = (t >> 7) + half * 2;  // token
        const int r  = t & 127;
        const int h  = r >> 3;               // head
        const int d0 = (r & 7) * 8;          // 8-d group
        const size_t ooff = (((size_t)bg * HH + h) * NN + n0 + tt) * 64 + d0;

        float qv[8], kv[8], vv[8];
#pragma unroll
        for (int i = 0; i < 8; i++) {
            int e = (d0 + i) * 16 + h;
            int s = SWIDX(e);
            qv[i] = sm3[0][tt][s] * QSCALE;
            kv[i] = sm3[1][tt][s];
            vv[i] = sm3[2][tt][s];
        }
        union { uint32_t u[4]; uint4 q4; } oq, ok, ov;
#pragma unroll
        for (int i = 0; i < 4; i++) {
            oq.u[i] = h2u(qv[2 * i], qv[2 * i + 1]);
            ok.u[i] = h2u(kv[2 * i], kv[2 * i + 1]);
            ov.u[i] = h2u(vv[2 * i], vv[2 * i + 1]);
        }
        *(uint4*)(g_Q + ooff) = oq.q4;
        *(uint4*)(g_K + ooff) = ok.q4;
        *(uint4*)(g_V + ooff) = ov.q4;
    }
#undef SWIDX
}

// ---------------------------------------------------------------------------
// Flash attention: 4 warps x 32 rows, 4-stage cp.async, one barrier/iter,
// 2 CTAs/SM (full 255 regs), permuted-EB vector loads. lsum via HADD2
// pre-reduction + 2 ones-B mma (was 8) to relieve the tensor pipe.
// ---------------------------------------------------------------------------
#define BR 128
#define BC 64
#define STAGES 4

struct Smem {
    __half K[STAGES][BC * 64];
    __half V[STAGES][BC * 64];
};
static constexpr int SMEM_BYTES = sizeof(Smem); // 64 KB

__device__ __forceinline__ void load_kv(char* smk, char* smv, const __half* kbase,
                                        const __half* vbase, int j, int tid) {
    const __half* kp = kbase + (size_t)j * BC * 64;
    const __half* vp = vbase + (size_t)j * BC * 64;
#pragma unroll
    for (int i = 0; i < 4; i++) {
        int c = tid + i * 128;          // 0..511
        int r = c >> 3, ch = c & 7;
        int dst = r * 128 + ((ch ^ (r & 7)) << 4);
        cp16(smk + dst, kp + r * 64 + ch * 8);
        cp16(smv + dst, vp + r * 64 + ch * 8);
    }
}

__global__ void __launch_bounds__(128, 2)
attn_kernel(float* __restrict__ out) {
    extern __shared__ char smraw[];
    Smem* sm = (Smem*)smraw;

    const int tid = threadIdx.x;
    const int lane = tid & 31, wid = tid >> 5;   // wid 0..3
    const int hd = blockIdx.z * HH + blockIdx.y;
    const int g  = blockIdx.z & 3;
    const int n0 = blockIdx.x * BR;
    const int ql = lane >> 2, qc = lane & 3;

    // Q fp16 A-fragments, resident: 2 m-halves x 4 k-blocks
    const __half* qp = g_Q + (((size_t)hd) * NN + n0 + wid * 32) * 64;
    uint32_t qa[2][4][4];
#pragma unroll
    for (int mh = 0; mh < 2; mh++)
#pragma unroll
        for (int kb = 0; kb < 4; kb++) {
            const __half* qr = qp + (mh * 16) * 64;
            qa[mh][kb][0] = *(const uint32_t*)(qr + (ql)     * 64 + kb * 16 + qc * 2);
            qa[mh][kb][1] = *(const uint32_t*)(qr + (ql + 8) * 64 + kb * 16 + qc * 2);
            qa[mh][kb][2] = *(const uint32_t*)(qr + (ql)     * 64 + kb * 16 + qc * 2 + 8);
            qa[mh][kb][3] = *(const uint32_t*)(qr + (ql + 8) * 64 + kb * 16 + qc * 2 + 8);
        }

    float o[2][8][4];
#pragma unroll
    for (int mh = 0; mh < 2; mh++)
#pragma unroll
        for (int nb = 0; nb < 8; nb++)
            o[mh][nb][0] = o[mh][nb][1] = o[mh][nb][2] = o[mh][nb][3] = 0.f;
    float lacc[2][4] = {{0.f, 0.f, 0.f, 0.f}, {0.f, 0.f, 0.f, 0.f}};

    const __half* kbase = g_K + ((size_t)hd) * NN * 64;
    const __half* vbase = g_V + ((size_t)hd) * NN * 64;

#pragma unroll
    for (int s = 0; s < 3; s++) {
        load_kv((char*)sm->K[s], (char*)sm->V[s], kbase, vbase, s, tid);
        asm volatile("cp.async.commit_group;");
    }

    // permuted-EB base: row (n0 + wid*32 + ql), within-tile offset qc*16
    const __half* ebbase =
        g_EB + ((size_t)g * NN + (n0 + wid * 32 + ql)) * NN + qc * 16;

#pragma unroll 1
    for (int j = 0; j < 16; j++) {
        const int buf = j & (STAGES - 1);

        // exp(-bias) fragments: 8 x LDG.128 (32B contiguous per row-half)
        uint32_t ebA[2][8], ebB[2][8];
#pragma unroll
        for (int mh = 0; mh < 2; mh++) {
            const __half* erA = ebbase + (size_t)(mh * 16) * NN + j * 64;
            const __half* erB = erA + (size_t)8 * NN;
            uint4 a0 = *(const uint4*)(erA);
            uint4 a1 = *(const uint4*)(erA + 8);
            uint4 b0 = *(const uint4*)(erB);
            uint4 b1 = *(const uint4*)(erB + 8);
            ebA[mh][0] = a0.x; ebA[mh][1] = a0.y; ebA[mh][2] = a0.z; ebA[mh][3] = a0.w;
            ebA[mh][4] = a1.x; ebA[mh][5] = a1.y; ebA[mh][6] = a1.z; ebA[mh][7] = a1.w;
            ebB[mh][0] = b0.x; ebB[mh][1] = b0.y; ebB[mh][2] = b0.z; ebB[mh][3] = b0.w;
            ebB[mh][4] = b1.x; ebB[mh][5] = b1.y; ebB[mh][6] = b1.z; ebB[mh][7] = b1.w;
        }

        if (j <= 13)      asm volatile("cp.async.wait_group 2;");
        else if (j == 14) asm volatile("cp.async.wait_group 1;");
        else              asm volatile("cp.async.wait_group 0;");
        __syncthreads();

        if (j + 3 < 16) {
            int nxt = (j + 3) & (STAGES - 1);
            load_kv((char*)sm->K[nxt], (char*)sm->V[nxt], kbase, vbase, j + 3, tid);
            asm volatile("cp.async.commit_group;");
        }

        // ---- S = Q K^T + SHIFT; each B-frag feeds both m-halves ----
        float s[2][8][4];
#pragma unroll
        for (int mh = 0; mh < 2; mh++)
#pragma unroll
            for (int nb = 0; nb < 8; nb++)
                s[mh][nb][0] = s[mh][nb][1] = s[mh][nb][2] = s[mh][nb][3] = SHIFT;
        {
            char* kb_sm = (char*)sm->K[buf];
            const int m = lane >> 3, r = lane & 7;
#pragma unroll
            for (int kb = 0; kb < 4; kb++) {
#pragma unroll
                for (int nbp = 0; nbp < 4; nbp++) {
                    int n = nbp * 16 + ((m >> 1) << 3) + r;
                    int ch = kb * 2 + (m & 1);
                    uint32_t addr = (uint32_t)__cvta_generic_to_shared(
                        kb_sm + n * 128 + ((ch ^ (n & 7)) << 4));
                    uint32_t b0, b1, b2, b3;
                    ldsm4(b0, b1, b2, b3, addr);
                    mma_f16(s[0][2 * nbp],     qa[0][kb], b0, b1);
                    mma_f16(s[0][2 * nbp + 1], qa[0][kb], b2, b3);
                    mma_f16(s[1][2 * nbp],     qa[1][kb], b0, b1);
                    mma_f16(s[1][2 * nbp + 1], qa[1][kb], b2, b3);
                }
            }
        }

        // ---- p = 2^(s-5) * exp(-bias) ----
        uint32_t pa[2][4][4];
#pragma unroll
        for (int mh = 0; mh < 2; mh++)
#pragma unroll
            for (int kb2 = 0; kb2 < 4; kb2++) {
                pa[mh][kb2][0] = hmul2u(ex2h2(h2u(s[mh][2*kb2][0],   s[mh][2*kb2][1])),   ebA[mh][2*kb2]);
                pa[mh][kb2][1] = hmul2u(ex2h2(h2u(s[mh][2*kb2][2],   s[mh][2*kb2][3])),   ebB[mh][2*kb2]);
                pa[mh][kb2][2] = hmul2u(ex2h2(h2u(s[mh][2*kb2+1][0], s[mh][2*kb2+1][1])), ebA[mh][2*kb2+1]);
                pa[mh][kb2][3] = hmul2u(ex2h2(h2u(s[mh][2*kb2+1][2], s[mh][2*kb2+1][3])), ebB[mh][2*kb2+1]);
            }

        // ---- l: HADD2-prereduce pa over kb2, then ONE ones-B mma per mh ----
#pragma unroll
        for (int mh = 0; mh < 2; mh++) {
            uint32_t s4[4];
#pragma unroll
            for (int i = 0; i < 4; i++)
                s4[i] = hadd2u(hadd2u(pa[mh][0][i], pa[mh][1][i]),
                               hadd2u(pa[mh][2][i], pa[mh][3][i]));
            mma_f16(lacc[mh], s4, ONES_H2, ONES_H2);
        }

        // ---- O += P V; each V-frag feeds both m-halves ----
        {
            char* vb_sm = (char*)sm->V[buf];
            const int lr = lane & 7, lm = lane >> 3;
#pragma unroll
            for (int kb2 = 0; kb2 < 4; kb2++) {
                const int krow = kb2 * 16 + lr + ((lm & 1) << 3);
#pragma unroll
                for (int nb2 = 0; nb2 < 4; nb2++) {
                    const int ch = nb2 * 2 + ((lm >> 1) & 1);
                    uint32_t addr = (uint32_t)__cvta_generic_to_shared(
                        vb_sm + krow * 128 + ((ch ^ (krow & 7)) << 4));
                    uint32_t v0, v1, v2, v3;
                    ldsm4t(v0, v1, v2, v3, addr);
                    mma_f16(o[0][nb2 * 2],     pa[0][kb2], v0, v1);
                    mma_f16(o[0][nb2 * 2 + 1], pa[0][kb2], v2, v3);
                    mma_f16(o[1][nb2 * 2],     pa[1][kb2], v0, v1);
                    mma_f16(o[1][nb2 * 2 + 1], pa[1][kb2], v2, v3);
                }
            }
        }
    }

    // ---- epilogue: normalize + store ----
#pragma unroll
    for (int mh = 0; mh < 2; mh++) {
        const float inv0 = 1.0f / lacc[mh][0], inv1 = 1.0f / lacc[mh][2];
        float* op = out + (((size_t)hd) * NN + n0 + wid * 32 + mh * 16 + ql) * 64 + qc * 2;
#pragma unroll
        for (int nb = 0; nb < 8; nb++) {
            float2 a = make_float2(o[mh][nb][0] * inv0, o[mh][nb][1] * inv0);
            float2 b = make_float2(o[mh][nb][2] * inv1, o[mh][nb][3] * inv1);
            *(float2*)(op + nb * 8) = a;
            *(float2*)(op + 8 * 64 + nb * 8) = b;
        }
    }
}

// ---------------------------------------------------------------------------
extern "C" void kernel_launch(void* const* d_in, const int* in_sizes, int n_in,
                              void* d_out, int out_size) {
    const float* q    = (const float*)d_in[0];
    const float* k    = (const float*)d_in[1];
    const float* v    = (const float*)d_in[2];
    const float* bias = (const float*)d_in[3];
    float* out = (float*)d_out;

    cudaFuncSetAttribute(attn_kernel, cudaFuncAttributeMaxDynamicSharedMemorySize,
                         SMEM_BYTES);

    prep_kernel<<<2560, 256>>>(q, k, v, bias);
    attn_kernel<<<dim3(NN / BR, HH, BGN), 128, SMEM_BYTES>>>(out);
}